// round 5
// baseline (speedup 1.0000x reference)
#include <cuda_runtime.h>
#include <cuda_bf16.h>
#include <cuda_fp16.h>
#include <cstdint>

#define EE 16384
#define NNODE 4096
#define HC 16384

// ------------- static scratch -------------
__device__ __align__(16) __half g_XLRh[(size_t)NNODE * 32768];  // [n][0:16384)=x_l, [16384:)=x_r
__device__ __align__(16) __half g_Rh[(size_t)NNODE * HC];       // relu(agg + bias), fp16
__device__ uint4 g_ApackHi[256 * 4 * 32];
__device__ uint4 g_ApackLo[256 * 4 * 32];
__device__ __align__(16) unsigned g_WpackHi[2 * 4 * 16384 * 8];
__device__ __align__(16) unsigned g_WpackLo[2 * 4 * 16384 * 8];
__device__ __align__(8) uint2 g_WoHi[1024 * 3 * 32];   // W_out fp16-hi fragments
__device__ __align__(8) uint2 g_WoLo[1024 * 3 * 32];   // W_out fp16-lo fragments
__device__ int g_deg[NNODE];
__device__ int g_rowptr[NNODE + 1];
__device__ int g_cursor[NNODE];
__device__ int g_esrc[EE];
__device__ int g_is64;
__device__ int g_src[EE];
__device__ int g_dstA[EE];

// ------------- helpers -------------
__device__ __forceinline__ void split2(float f0, float f1, unsigned &hi, unsigned &lo) {
    __nv_bfloat162 hv = __floats2bfloat162_rn(f0, f1);
    hi = *reinterpret_cast<unsigned *>(&hv);
    __nv_bfloat162 lv = __floats2bfloat162_rn(f0 - __low2float(hv), f1 - __high2float(hv));
    lo = *reinterpret_cast<unsigned *>(&lv);
}
__device__ __forceinline__ void mma_bf16(float &c0, float &c1, float &c2, float &c3,
                                         unsigned a0, unsigned a1, unsigned a2, unsigned a3,
                                         unsigned b0, unsigned b1) {
    asm volatile("mma.sync.aligned.m16n8k16.row.col.f32.bf16.bf16.f32 "
                 "{%0,%1,%2,%3}, {%4,%5,%6,%7}, {%8,%9}, {%0,%1,%2,%3};\n"
                 : "+f"(c0), "+f"(c1), "+f"(c2), "+f"(c3)
                 : "r"(a0), "r"(a1), "r"(a2), "r"(a3), "r"(b0), "r"(b1));
}
__device__ __forceinline__ void mma_f16(float &c0, float &c1, float &c2, float &c3,
                                        unsigned a0, unsigned a1, unsigned a2, unsigned a3,
                                        unsigned b0, unsigned b1) {
    asm volatile("mma.sync.aligned.m16n8k16.row.col.f32.f16.f16.f32 "
                 "{%0,%1,%2,%3}, {%4,%5,%6,%7}, {%8,%9}, {%0,%1,%2,%3};\n"
                 : "+f"(c0), "+f"(c1), "+f"(c2), "+f"(c3)
                 : "r"(a0), "r"(a1), "r"(a2), "r"(a3), "r"(b0), "r"(b1));
}
__device__ __forceinline__ float lrelu(float v) { return fmaxf(v, 0.f) + 0.2f * fminf(v, 0.f); }
__device__ __forceinline__ void h8_to_f(const uint4 &u, float *f) {
    const __half2 *p = (const __half2 *)&u;
#pragma unroll
    for (int i = 0; i < 4; i++) {
        float2 v = __half22float2(p[i]);
        f[2 * i] = v.x;
        f[2 * i + 1] = v.y;
    }
}

// ------------- edge_index dtype detection + sanitized extraction -------------
__global__ void detect_k(const unsigned *__restrict__ w) {
    int is64 = 1;
    for (int i = 1; i < 64; i += 2)
        if (w[i] != 0u) { is64 = 0; break; }
    g_is64 = is64;
}
__global__ void loadidx_k(const unsigned *__restrict__ w) {
    int e = blockIdx.x * 256 + threadIdx.x;
    if (e < EE) {
        int s, d;
        if (g_is64) {
            s = (int)w[2 * e];
            d = (int)w[2 * (EE + e)];
        } else {
            s = (int)w[e];
            d = (int)w[EE + e];
        }
        g_src[e] = s & (NNODE - 1);
        g_dstA[e] = d & (NNODE - 1);
    }
}

// ------------- pack A (x) into mma fragments -------------
__global__ void pack_a_k(const float *__restrict__ x) {
    int t = blockIdx.x * 256 + threadIdx.x;  // 32768 threads
    int lane = t & 31, kt = (t >> 5) & 3, mt = t >> 7;
    int gid = lane >> 2, tig = lane & 3;
    int r0 = mt * 16 + gid, r1 = r0 + 8;
    int c0 = kt * 16 + tig * 2, c1 = c0 + 8;
    uint4 hi, lo;
    split2(x[r0 * 64 + c0], x[r0 * 64 + c0 + 1], hi.x, lo.x);
    split2(x[r1 * 64 + c0], x[r1 * 64 + c0 + 1], hi.y, lo.y);
    split2(x[r0 * 64 + c1], x[r0 * 64 + c1 + 1], hi.z, lo.z);
    split2(x[r1 * 64 + c1], x[r1 * 64 + c1 + 1], hi.w, lo.w);
    g_ApackHi[(mt * 4 + kt) * 32 + lane] = hi;
    g_ApackLo[(mt * 4 + kt) * 32 + lane] = lo;
}

// ------------- pack W_l/W_r into B fragments -------------
__global__ void pack_w_k(const float *__restrict__ Wl, const float *__restrict__ Wr) {
    unsigned t = blockIdx.x * 256u + threadIdx.x;  // 1,048,576 threads
    unsigned mat = t >> 19, idx = t & 524287u;
    unsigned kt = idx >> 17, rem = idx & 131071u;
    unsigned n = rem >> 3, j = rem & 7;
    unsigned q = j >> 1, s = j & 1;
    unsigned k = kt * 16 + s * 8 + q * 2;
    const float *W = mat ? Wr : Wl;
    unsigned hi, lo;
    split2(W[k * HC + n], W[(k + 1) * HC + n], hi, lo);
    g_WpackHi[t] = hi;
    g_WpackLo[t] = lo;
}

// ------------- pack W_out into fp16 hi/lo B fragments (N padded to 24) -------------
__global__ void pack_wout_k(const float *__restrict__ Wout) {
    int t = blockIdx.x * 256 + threadIdx.x;  // 98304 threads
    int kt = t / 96, rem = t % 96;
    int nt = rem >> 5, lane = rem & 31;
    int gid = lane >> 2, tig = lane & 3;
    int n = nt * 8 + gid;
    int k0 = kt * 16 + tig * 2;
    float f[4];
    if (n < 20) {
        f[0] = Wout[k0 * 20 + n];
        f[1] = Wout[(k0 + 1) * 20 + n];
        f[2] = Wout[(k0 + 8) * 20 + n];
        f[3] = Wout[(k0 + 9) * 20 + n];
    } else {
        f[0] = f[1] = f[2] = f[3] = 0.f;
    }
    __half h[4];
    float l[4];
#pragma unroll
    for (int i = 0; i < 4; i++) {
        h[i] = __float2half_rn(f[i]);
        l[i] = f[i] - __half2float(h[i]);
    }
    uint2 bh, bl;
    __half2 t0 = __halves2half2(h[0], h[1]), t1 = __halves2half2(h[2], h[3]);
    bh.x = *(unsigned *)&t0;
    bh.y = *(unsigned *)&t1;
    __half2 t2 = __floats2half2_rn(l[0], l[1]), t3 = __floats2half2_rn(l[2], l[3]);
    bl.x = *(unsigned *)&t2;
    bl.y = *(unsigned *)&t3;
    int o = (kt * 3 + nt) * 32 + lane;
    g_WoHi[o] = bh;
    g_WoLo[o] = bl;
}

// ------------- CSR by destination -------------
__global__ void zero_deg_k() {
    int t = blockIdx.x * 256 + threadIdx.x;
    if (t < NNODE) g_deg[t] = 0;
}
__global__ void hist_k() {
    int e = blockIdx.x * 256 + threadIdx.x;
    if (e < EE) atomicAdd(&g_deg[g_dstA[e]], 1);
}
__global__ void scan_k() {
    __shared__ int sm[1024];
    int t = threadIdx.x, b = t * 4;
    int d0 = g_deg[b], d1 = g_deg[b + 1], d2 = g_deg[b + 2], d3 = g_deg[b + 3];
    int p1 = d0, p2 = d0 + d1, p3 = p2 + d2, tot = p3 + d3;
    sm[t] = tot;
    __syncthreads();
    for (int off = 1; off < 1024; off <<= 1) {
        int y = (t >= off) ? sm[t - off] : 0;
        __syncthreads();
        sm[t] += y;
        __syncthreads();
    }
    int excl = (t > 0) ? sm[t - 1] : 0;
    g_rowptr[b] = excl;          g_cursor[b] = excl;
    g_rowptr[b + 1] = excl + p1; g_cursor[b + 1] = excl + p1;
    g_rowptr[b + 2] = excl + p2; g_cursor[b + 2] = excl + p2;
    g_rowptr[b + 3] = excl + p3; g_cursor[b + 3] = excl + p3;
    if (t == 1023) g_rowptr[NNODE] = sm[1023];
}
__global__ void scatter_k() {
    int e = blockIdx.x * 256 + threadIdx.x;
    if (e < EE) {
        int dst = g_dstA[e];
        g_esrc[atomicAdd(&g_cursor[dst], 1)] = g_src[e];
    }
}

// ------------- GEMM: XLR = x @ [W_l | W_r] (bf16 hi/lo split mma, fp16 out) -------------
__global__ void __launch_bounds__(256) gemm_k() {
    __shared__ uint4 sB[1024];
    int t = threadIdx.x;
    int n0 = blockIdx.x * 64;
    int mat = (n0 >= HC) ? 1 : 0;
    int nn = n0 - mat * HC;
    const uint4 *Vh = ((const uint4 *)g_WpackHi) + (size_t)mat * 131072;
    const uint4 *Vl = ((const uint4 *)g_WpackLo) + (size_t)mat * 131072;
#pragma unroll
    for (int i = 0; i < 4; i++) {
        int idx = i * 256 + t;
        int isLo = idx >> 9, w = idx & 511;
        int kt = w >> 7, u = w & 127;
        const uint4 *src = isLo ? Vl : Vh;
        sB[isLo * 512 + kt * 128 + u] = src[(kt * 16384 + nn) * 2 + u];
    }
    int warp = t >> 5, lane = t & 31;
    int gid = lane >> 2, tig = lane & 3;
    int mt = blockIdx.y * 8 + warp;
    uint4 aH[4], aL[4];
#pragma unroll
    for (int kt = 0; kt < 4; kt++) {
        aH[kt] = g_ApackHi[(mt * 4 + kt) * 32 + lane];
        aL[kt] = g_ApackLo[(mt * 4 + kt) * 32 + lane];
    }
    __syncthreads();
    const unsigned *sH = (const unsigned *)sB;
    const unsigned *sL = sH + 2048;
    size_t rowoff = (size_t)(mt * 16 + gid) * 32768 + n0;
    __half *o0 = g_XLRh + rowoff;
    __half *o1 = g_XLRh + rowoff + (size_t)8 * 32768;
#pragma unroll
    for (int nt = 0; nt < 8; nt++) {
        float c0 = 0.f, c1 = 0.f, c2 = 0.f, c3 = 0.f;
#pragma unroll
        for (int kt = 0; kt < 4; kt++) {
            int bi = kt * 512 + (nt * 8 + gid) * 8 + tig * 2;
            unsigned bh0 = sH[bi], bh1 = sH[bi + 1];
            unsigned bl0 = sL[bi], bl1 = sL[bi + 1];
            mma_bf16(c0, c1, c2, c3, aH[kt].x, aH[kt].y, aH[kt].z, aH[kt].w, bh0, bh1);
            mma_bf16(c0, c1, c2, c3, aH[kt].x, aH[kt].y, aH[kt].z, aH[kt].w, bl0, bl1);
            mma_bf16(c0, c1, c2, c3, aL[kt].x, aL[kt].y, aL[kt].z, aL[kt].w, bh0, bh1);
        }
        int col = nt * 8 + tig * 2;
        *(__half2 *)(o0 + col) = __floats2half2_rn(c0, c1);
        *(__half2 *)(o1 + col) = __floats2half2_rn(c2, c3);
    }
}

// ------------- fused attention: one WARP per (dst, head), barrier-free -------------
__global__ void __launch_bounds__(128) attn_k(const float *__restrict__ att,
                                              const float *__restrict__ bias) {
    int w = threadIdx.x >> 5, lane = threadIdx.x & 31;
    int p = blockIdx.x * 4 + w;     // head-major: 65536 pairs
    int h = p >> 12, dst = p & (NNODE - 1);
    // lane owns channels {c*256 + lane*8 .. +8, c=0..3}
    float xr[32], at[32], acc[32];
    {
        const uint4 *xr4 = (const uint4 *)(g_XLRh + (size_t)dst * 32768 + HC + h * 1024);
        const float4 *at4 = (const float4 *)(att + h * 1024);
#pragma unroll
        for (int c = 0; c < 4; c++) {
            h8_to_f(xr4[c * 32 + lane], xr + c * 8);
            float4 a0 = at4[(c * 256 + lane * 8) >> 2], a1 = at4[((c * 256 + lane * 8) >> 2) + 1];
            at[c * 8 + 0] = a0.x; at[c * 8 + 1] = a0.y; at[c * 8 + 2] = a0.z; at[c * 8 + 3] = a0.w;
            at[c * 8 + 4] = a1.x; at[c * 8 + 5] = a1.y; at[c * 8 + 6] = a1.z; at[c * 8 + 7] = a1.w;
        }
    }
#pragma unroll
    for (int j = 0; j < 32; j++) acc[j] = 0.f;
    float m = -1e30f, s = 0.f;
    int rp = g_rowptr[dst];
    int deg = g_rowptr[dst + 1] - rp;
    for (int i = 0; i <= deg; i++) {  // last = self-loop
        int src = (i < deg) ? g_esrc[rp + i] : dst;
        const uint4 *xl4 = (const uint4 *)(g_XLRh + (size_t)src * 32768 + h * 1024);
        float xl[32];
#pragma unroll
        for (int c = 0; c < 4; c++) h8_to_f(xl4[c * 32 + lane], xl + c * 8);
        float pp = 0.f;
#pragma unroll
        for (int j = 0; j < 32; j++) pp = fmaf(at[j], lrelu(xl[j] + xr[j]), pp);
        pp += __shfl_xor_sync(0xffffffffu, pp, 16);
        pp += __shfl_xor_sync(0xffffffffu, pp, 8);
        pp += __shfl_xor_sync(0xffffffffu, pp, 4);
        pp += __shfl_xor_sync(0xffffffffu, pp, 2);
        pp += __shfl_xor_sync(0xffffffffu, pp, 1);
        float mn = fmaxf(m, pp);
        float sc = __expf(m - mn);
        float wg = __expf(pp - mn);
        s = s * sc + wg;
#pragma unroll
        for (int j = 0; j < 32; j++) acc[j] = fmaf(acc[j], sc, wg * xl[j]);
        m = mn;
    }
    float inv = 1.f / (s + 1e-16f);
    const float4 *b4 = (const float4 *)(bias + h * 1024);
    uint4 *Ro = (uint4 *)(g_Rh + (size_t)dst * HC + h * 1024);
#pragma unroll
    for (int c = 0; c < 4; c++) {
        float4 b0 = b4[(c * 256 + lane * 8) >> 2], b1 = b4[((c * 256 + lane * 8) >> 2) + 1];
        float bi[8] = {b0.x, b0.y, b0.z, b0.w, b1.x, b1.y, b1.z, b1.w};
        uint4 ou;
        __half2 *op = (__half2 *)&ou;
#pragma unroll
        for (int j = 0; j < 4; j++) {
            float v0 = fmaxf(fmaf(acc[c * 8 + 2 * j], inv, bi[2 * j]), 0.f);
            float v1 = fmaxf(fmaf(acc[c * 8 + 2 * j + 1], inv, bi[2 * j + 1]), 0.f);
            op[j] = __floats2half2_rn(v0, v1);
        }
        Ro[c * 32 + lane] = ou;
    }
}

// ------------- output GEMM (tensor core): z = R @ W_out + b_out -------------
__global__ void zinit_k(float *__restrict__ out, const float *__restrict__ bout) {
    int i = blockIdx.x * 256 + threadIdx.x;  // 81920 exactly
    out[i] = bout[i % 20];
}
__global__ void __launch_bounds__(256) zout_k(float *__restrict__ out) {
    __shared__ __align__(16) char sA[128 * 128];  // 128 rows x 64 halves, SW128
    int t = threadIdx.x, warp = t >> 5, lane = t & 31;
    int m0 = blockIdx.x * 128;
    int k0 = blockIdx.y * 1024;
    float c[3][4];
#pragma unroll
    for (int nt = 0; nt < 3; nt++)
#pragma unroll
        for (int j = 0; j < 4; j++) c[nt][j] = 0.f;
    int r0 = warp * 16;
    // ldmatrix per-lane source address components
    int mrow = r0 + (lane & 7) + ((lane >> 3) & 1) * 8;
    int khalf = ((lane >> 4) & 1) * 16;
    for (int ch = 0; ch < 16; ch++) {
        int kc = k0 + ch * 64;
        __syncthreads();
#pragma unroll
        for (int q = 0; q < 4; q++) {
            int i = t + q * 256;  // 0..1023
            int row = i >> 3, u = i & 7;
            uint4 v = *(const uint4 *)(g_Rh + (size_t)(m0 + row) * HC + kc + u * 8);
            int b = (row * 128 + u * 16) ^ ((row & 7) * 16);
            *(uint4 *)(sA + b) = v;
        }
        __syncthreads();
#pragma unroll
        for (int kt = 0; kt < 4; kt++) {
            int b = (mrow * 128 + kt * 32 + khalf) ^ ((mrow & 7) * 16);
            unsigned sa = (unsigned)__cvta_generic_to_shared(sA + b);
            unsigned a0, a1, a2, a3;
            asm volatile("ldmatrix.sync.aligned.m8n8.x4.shared.b16 {%0,%1,%2,%3}, [%4];"
                         : "=r"(a0), "=r"(a1), "=r"(a2), "=r"(a3) : "r"(sa));
            int ktg = ((kc >> 4) + kt) * 3;
#pragma unroll
            for (int nt = 0; nt < 3; nt++) {
                uint2 bh = g_WoHi[(ktg + nt) * 32 + lane];
                uint2 bl = g_WoLo[(ktg + nt) * 32 + lane];
                mma_f16(c[nt][0], c[nt][1], c[nt][2], c[nt][3], a0, a1, a2, a3, bh.x, bh.y);
                mma_f16(c[nt][0], c[nt][1], c[nt][2], c[nt][3], a0, a1, a2, a3, bl.x, bl.y);
            }
        }
    }
    int gid = lane >> 2, tig = lane & 3;
    int row = m0 + r0 + gid;
#pragma unroll
    for (int nt = 0; nt < 3; nt++) {
        int col = nt * 8 + tig * 2;
        if (col < 20) {
            atomicAdd(&out[row * 20 + col], c[nt][0]);
            atomicAdd(&out[(row + 8) * 20 + col], c[nt][2]);
        }
        if (col + 1 < 20) {
            atomicAdd(&out[row * 20 + col + 1], c[nt][1]);
            atomicAdd(&out[(row + 8) * 20 + col + 1], c[nt][3]);
        }
    }
}

extern "C" void kernel_launch(void *const *d_in, const int *in_sizes, int n_in,
                              void *d_out, int out_size) {
    const float *x = (const float *)d_in[0];
    const unsigned *ei = (const unsigned *)d_in[1];
    const float *Wl = (const float *)d_in[2];
    const float *Wr = (const float *)d_in[3];
    const float *att = (const float *)d_in[4];
    const float *bias = (const float *)d_in[5];
    const float *Wout = (const float *)d_in[6];
    const float *bout = (const float *)d_in[7];
    float *out = (float *)d_out;

    pack_a_k<<<128, 256>>>(x);          // 0
    pack_w_k<<<4096, 256>>>(Wl, Wr);    // 1
    detect_k<<<1, 1>>>(ei);             // 2
    gemm_k<<<dim3(512, 32), 256>>>();   // 3  <- ncu -s 5 capture slot
    loadidx_k<<<64, 256>>>(ei);         // 4
    zero_deg_k<<<16, 256>>>();          // 5
    hist_k<<<64, 256>>>();              // 6
    scan_k<<<1, 1024>>>();              // 7
    scatter_k<<<64, 256>>>();           // 8
    pack_wout_k<<<384, 256>>>(Wout);    // 9
    zinit_k<<<320, 256>>>(out, bout);   // 10
    attn_k<<<16384, 128>>>(att, bias);  // 11
    zout_k<<<dim3(32, 16), 256>>>(out); // 12
}

// round 6
// speedup vs baseline: 1.1414x; 1.1414x over previous
#include <cuda_runtime.h>
#include <cuda_bf16.h>
#include <cuda_fp16.h>
#include <cstdint>

#define EE 16384
#define NNODE 4096
#define HC 16384

// ------------- static scratch -------------
__device__ __align__(16) __half g_XLRh[(size_t)NNODE * 32768];  // [n][0:16384)=x_l, [16384:)=x_r (phys-permuted cols)
__device__ __align__(16) __half g_Rh[(size_t)NNODE * HC];       // relu(agg + bias), fp16, phys-permuted
__device__ __align__(16) uint4 g_Apack[256 * 8 * 32];           // x tf32 A-fragments [mt][ks][lane]
__device__ __align__(16) uint2 g_Wb[512 * 8 * 8 * 32];          // [W_l|W_r] tf32 B-fragments [nb][nt][ks][lane]
__device__ __align__(8) uint2 g_WoHi[1024 * 3 * 32];            // W_out fp16-hi fragments
__device__ __align__(8) uint2 g_WoLo[1024 * 3 * 32];            // W_out fp16-lo fragments
__device__ __align__(16) float g_attP[HC];                      // att, column-permuted
__device__ __align__(16) float g_biasP[HC];                     // bias, column-permuted
__device__ int g_deg[NNODE];
__device__ int g_rowptr[NNODE + 1];
__device__ int g_cursor[NNODE];
__device__ int g_esrc[EE];
__device__ int g_is64;
__device__ int g_src[EE];
__device__ int g_dstA[EE];

// ------------- helpers -------------
__device__ __forceinline__ unsigned f2tf32(float f) {
    unsigned r;
    asm("cvt.rna.tf32.f32 %0, %1;" : "=r"(r) : "f"(f));
    return r;
}
__device__ __forceinline__ void mma_tf32(float *c, const uint4 &a, const uint2 &b) {
    asm volatile("mma.sync.aligned.m16n8k8.row.col.f32.tf32.tf32.f32 "
                 "{%0,%1,%2,%3}, {%4,%5,%6,%7}, {%8,%9}, {%0,%1,%2,%3};\n"
                 : "+f"(c[0]), "+f"(c[1]), "+f"(c[2]), "+f"(c[3])
                 : "r"(a.x), "r"(a.y), "r"(a.z), "r"(a.w), "r"(b.x), "r"(b.y));
}
__device__ __forceinline__ void mma_f16(float &c0, float &c1, float &c2, float &c3,
                                        unsigned a0, unsigned a1, unsigned a2, unsigned a3,
                                        unsigned b0, unsigned b1) {
    asm volatile("mma.sync.aligned.m16n8k16.row.col.f32.f16.f16.f32 "
                 "{%0,%1,%2,%3}, {%4,%5,%6,%7}, {%8,%9}, {%0,%1,%2,%3};\n"
                 : "+f"(c0), "+f"(c1), "+f"(c2), "+f"(c3)
                 : "r"(a0), "r"(a1), "r"(a2), "r"(a3), "r"(b0), "r"(b1));
}
__device__ __forceinline__ float lrelu(float v) { return fmaxf(v, 0.f) + 0.2f * fminf(v, 0.f); }
__device__ __forceinline__ void h8_to_f(const uint4 &u, float *f) {
    const __half2 *p = (const __half2 *)&u;
#pragma unroll
    for (int i = 0; i < 4; i++) {
        float2 v = __half22float2(p[i]);
        f[2 * i] = v.x;
        f[2 * i + 1] = v.y;
    }
}
// physical column -> logical column, within each 32-col block
__device__ __forceinline__ int Lr(int r) {
    int p = r & 31;
    return (r & ~31) | ((((p >> 1) & 3) << 3) | (((p >> 3) & 3) << 1) | (p & 1));
}

// ------------- edge_index dtype detection + sanitized extraction -------------
__global__ void detect_k(const unsigned *__restrict__ w) {
    int is64 = 1;
    for (int i = 1; i < 64; i += 2)
        if (w[i] != 0u) { is64 = 0; break; }
    g_is64 = is64;
}
__global__ void loadidx_k(const unsigned *__restrict__ w) {
    int e = blockIdx.x * 256 + threadIdx.x;
    if (e < EE) {
        int s, d;
        if (g_is64) {
            s = (int)w[2 * e];
            d = (int)w[2 * (EE + e)];
        } else {
            s = (int)w[e];
            d = (int)w[EE + e];
        }
        g_src[e] = s & (NNODE - 1);
        g_dstA[e] = d & (NNODE - 1);
    }
}

// ------------- pack A (x) into tf32 fragments -------------
__global__ void pack_a_k(const float *__restrict__ x) {
    int u = blockIdx.x * 256 + threadIdx.x;  // 65536 threads
    int lane = u & 31, ks = (u >> 5) & 7, mt = u >> 8;
    int gid = lane >> 2, tig = lane & 3;
    const float *r0 = x + (mt * 16 + gid) * 64;
    const float *r1 = r0 + 8 * 64;
    uint4 a;
    a.x = f2tf32(r0[ks * 8 + tig]);
    a.y = f2tf32(r1[ks * 8 + tig]);
    a.z = f2tf32(r0[ks * 8 + tig + 4]);
    a.w = f2tf32(r1[ks * 8 + tig + 4]);
    g_Apack[u] = a;
}

// ------------- pack W_l/W_r into tf32 B fragments -------------
__global__ void pack_w_k(const float *__restrict__ Wl, const float *__restrict__ Wr) {
    unsigned u = blockIdx.x * 256u + threadIdx.x;  // 1,048,576 threads
    int lane = u & 31, ks = (u >> 5) & 7, nt = (u >> 8) & 7;
    int nb = u >> 11;
    int gid = lane >> 2, tig = lane & 3;
    int ncat = nb * 64 + nt * 8 + gid;
    const float *W = (ncat >= HC) ? Wr : Wl;
    int n = ncat & (HC - 1);
    int k0 = ks * 8 + tig;
    uint2 b;
    b.x = f2tf32(W[k0 * HC + n]);
    b.y = f2tf32(W[(k0 + 4) * HC + n]);
    g_Wb[u] = b;
}

// ------------- pack W_out into fp16 hi/lo B fragments (perm rows, N padded to 24) -------
__global__ void pack_wout_k(const float *__restrict__ Wout) {
    int t = blockIdx.x * 256 + threadIdx.x;  // 98304 threads
    int kt = t / 96, rem = t % 96;
    int nt = rem >> 5, lane = rem & 31;
    int gid = lane >> 2, tig = lane & 3;
    int n = nt * 8 + gid;
    int k0 = kt * 16 + tig * 2;
    float f[4];
    if (n < 20) {
        f[0] = Wout[Lr(k0) * 20 + n];
        f[1] = Wout[Lr(k0 + 1) * 20 + n];
        f[2] = Wout[Lr(k0 + 8) * 20 + n];
        f[3] = Wout[Lr(k0 + 9) * 20 + n];
    } else {
        f[0] = f[1] = f[2] = f[3] = 0.f;
    }
    __half h[4];
    float l[4];
#pragma unroll
    for (int i = 0; i < 4; i++) {
        h[i] = __float2half_rn(f[i]);
        l[i] = f[i] - __half2float(h[i]);
    }
    uint2 bh, bl;
    __half2 t0 = __halves2half2(h[0], h[1]), t1 = __halves2half2(h[2], h[3]);
    bh.x = *(unsigned *)&t0;
    bh.y = *(unsigned *)&t1;
    __half2 t2 = __floats2half2_rn(l[0], l[1]), t3 = __floats2half2_rn(l[2], l[3]);
    bl.x = *(unsigned *)&t2;
    bl.y = *(unsigned *)&t3;
    int o = (kt * 3 + nt) * 32 + lane;
    g_WoHi[o] = bh;
    g_WoLo[o] = bl;
}

// ------------- permute att / bias to physical column order -------------
__global__ void pack_ab_k(const float *__restrict__ att, const float *__restrict__ bias) {
    int c = blockIdx.x * 256 + threadIdx.x;  // 16384
    int L = Lr(c);
    g_attP[c] = att[L];
    g_biasP[c] = bias[L];
}

// ------------- CSR by destination -------------
__global__ void zero_deg_k() {
    int t = blockIdx.x * 256 + threadIdx.x;
    if (t < NNODE) g_deg[t] = 0;
}
__global__ void hist_k() {
    int e = blockIdx.x * 256 + threadIdx.x;
    if (e < EE) atomicAdd(&g_deg[g_dstA[e]], 1);
}
__global__ void scan_k() {
    __shared__ int sm[1024];
    int t = threadIdx.x, b = t * 4;
    int d0 = g_deg[b], d1 = g_deg[b + 1], d2 = g_deg[b + 2], d3 = g_deg[b + 3];
    int p1 = d0, p2 = d0 + d1, p3 = p2 + d2, tot = p3 + d3;
    sm[t] = tot;
    __syncthreads();
    for (int off = 1; off < 1024; off <<= 1) {
        int y = (t >= off) ? sm[t - off] : 0;
        __syncthreads();
        sm[t] += y;
        __syncthreads();
    }
    int excl = (t > 0) ? sm[t - 1] : 0;
    g_rowptr[b] = excl;          g_cursor[b] = excl;
    g_rowptr[b + 1] = excl + p1; g_cursor[b + 1] = excl + p1;
    g_rowptr[b + 2] = excl + p2; g_cursor[b + 2] = excl + p2;
    g_rowptr[b + 3] = excl + p3; g_cursor[b + 3] = excl + p3;
    if (t == 1023) g_rowptr[NNODE] = sm[1023];
}
__global__ void scatter_k() {
    int e = blockIdx.x * 256 + threadIdx.x;
    if (e < EE) {
        int dst = g_dstA[e];
        g_esrc[atomicAdd(&g_cursor[dst], 1)] = g_src[e];
    }
}

// ------------- GEMM: XLR = x @ [W_l | W_r]  (tf32 single pass, MT=2, coalesced stores)
__global__ void __launch_bounds__(256) gemm_k() {
    __shared__ uint2 sB[2048];  // [nt(8)][ks(8)][lane(32)] = 16KB
    int t = threadIdx.x, warp = t >> 5, lane = t & 31;
    int gid = lane >> 2, tig = lane & 3;
    int nb = blockIdx.x;   // 512: 64 cols each
    int mb = blockIdx.y;   // 16: 256 rows each
    {
        const uint4 *src = (const uint4 *)(g_Wb + nb * 2048);
        uint4 *dst = (uint4 *)sB;
#pragma unroll
        for (int i = 0; i < 4; i++) dst[i * 256 + t] = src[i * 256 + t];
    }
    int mt0 = (mb * 8 + warp) * 2;  // two m-tiles per warp
    uint4 A0[8], A1[8];
#pragma unroll
    for (int ks = 0; ks < 8; ks++) {
        A0[ks] = g_Apack[(mt0 * 8 + ks) * 32 + lane];
        A1[ks] = g_Apack[((mt0 + 1) * 8 + ks) * 32 + lane];
    }
    __syncthreads();
    float c[2][8][4];
#pragma unroll
    for (int m = 0; m < 2; m++)
#pragma unroll
        for (int nt = 0; nt < 8; nt++)
#pragma unroll
            for (int j = 0; j < 4; j++) c[m][nt][j] = 0.f;
#pragma unroll
    for (int nt = 0; nt < 8; nt++) {
#pragma unroll
        for (int ks = 0; ks < 8; ks++) {
            uint2 b = sB[(nt * 8 + ks) * 32 + lane];
            mma_tf32(c[0][nt], A0[ks], b);
            mma_tf32(c[1][nt], A1[ks], b);
        }
    }
    // stores: phys col = nb*64 + (nt>>2)*32 + tig*8 + (nt&3)*2 + j  -> uint4 per (row, b32)
#pragma unroll
    for (int m = 0; m < 2; m++) {
        int rbase = (mt0 + m) * 16;
#pragma unroll
        for (int half = 0; half < 2; half++) {  // row gid / gid+8 (c pair offset)
            int row = rbase + gid + half * 8;
            __half *orow = g_XLRh + (size_t)row * 32768 + nb * 64 + tig * 8;
#pragma unroll
            for (int b32 = 0; b32 < 2; b32++) {
                uint4 ou;
                __half2 *op = (__half2 *)&ou;
#pragma unroll
                for (int q = 0; q < 4; q++) {
                    int nt = b32 * 4 + q;
                    op[q] = __floats2half2_rn(c[m][nt][half * 2], c[m][nt][half * 2 + 1]);
                }
                *(uint4 *)(orow + b32 * 32) = ou;
            }
        }
    }
}

// ------------- fused attention: one WARP per (dst, head), barrier-free -------------
__global__ void __launch_bounds__(128) attn_k() {
    int w = threadIdx.x >> 5, lane = threadIdx.x & 31;
    int p = blockIdx.x * 4 + w;  // head-major: 65536 pairs
    int h = p >> 12, dst = p & (NNODE - 1);
    float xr[32], at[32], acc[32];
    {
        const uint4 *xr4 = (const uint4 *)(g_XLRh + (size_t)dst * 32768 + HC + h * 1024);
        const float4 *at4 = (const float4 *)(g_attP + h * 1024);
#pragma unroll
        for (int c = 0; c < 4; c++) {
            h8_to_f(xr4[c * 32 + lane], xr + c * 8);
            float4 a0 = at4[(c * 256 + lane * 8) >> 2], a1 = at4[((c * 256 + lane * 8) >> 2) + 1];
            at[c * 8 + 0] = a0.x; at[c * 8 + 1] = a0.y; at[c * 8 + 2] = a0.z; at[c * 8 + 3] = a0.w;
            at[c * 8 + 4] = a1.x; at[c * 8 + 5] = a1.y; at[c * 8 + 6] = a1.z; at[c * 8 + 7] = a1.w;
        }
    }
#pragma unroll
    for (int j = 0; j < 32; j++) acc[j] = 0.f;
    float m = -1e30f, s = 0.f;
    int rp = g_rowptr[dst];
    int deg = g_rowptr[dst + 1] - rp;
    for (int i = 0; i <= deg; i++) {  // last = self-loop
        int src = (i < deg) ? g_esrc[rp + i] : dst;
        const uint4 *xl4 = (const uint4 *)(g_XLRh + (size_t)src * 32768 + h * 1024);
        float xl[32];
#pragma unroll
        for (int c = 0; c < 4; c++) h8_to_f(xl4[c * 32 + lane], xl + c * 8);
        float pp = 0.f;
#pragma unroll
        for (int j = 0; j < 32; j++) pp = fmaf(at[j], lrelu(xl[j] + xr[j]), pp);
        pp += __shfl_xor_sync(0xffffffffu, pp, 16);
        pp += __shfl_xor_sync(0xffffffffu, pp, 8);
        pp += __shfl_xor_sync(0xffffffffu, pp, 4);
        pp += __shfl_xor_sync(0xffffffffu, pp, 2);
        pp += __shfl_xor_sync(0xffffffffu, pp, 1);
        float mn = fmaxf(m, pp);
        float sc = __expf(m - mn);
        float wg = __expf(pp - mn);
        s = s * sc + wg;
#pragma unroll
        for (int j = 0; j < 32; j++) acc[j] = fmaf(acc[j], sc, wg * xl[j]);
        m = mn;
    }
    float inv = 1.f / (s + 1e-16f);
    const float4 *b4 = (const float4 *)(g_biasP + h * 1024);
    uint4 *Ro = (uint4 *)(g_Rh + (size_t)dst * HC + h * 1024);
#pragma unroll
    for (int c = 0; c < 4; c++) {
        float4 b0 = b4[(c * 256 + lane * 8) >> 2], b1 = b4[((c * 256 + lane * 8) >> 2) + 1];
        float bi[8] = {b0.x, b0.y, b0.z, b0.w, b1.x, b1.y, b1.z, b1.w};
        uint4 ou;
        __half2 *op = (__half2 *)&ou;
#pragma unroll
        for (int j = 0; j < 4; j++) {
            float v0 = fmaxf(fmaf(acc[c * 8 + 2 * j], inv, bi[2 * j]), 0.f);
            float v1 = fmaxf(fmaf(acc[c * 8 + 2 * j + 1], inv, bi[2 * j + 1]), 0.f);
            op[j] = __floats2half2_rn(v0, v1);
        }
        Ro[c * 32 + lane] = ou;
    }
}

// ------------- output GEMM (tensor core): z = R @ W_out + b_out -------------
__global__ void zinit_k(float *__restrict__ out, const float *__restrict__ bout) {
    int i = blockIdx.x * 256 + threadIdx.x;  // 81920 exactly
    out[i] = bout[i % 20];
}
__global__ void __launch_bounds__(256) zout_k(float *__restrict__ out) {
    __shared__ __align__(16) char sA[128 * 128];  // 128 rows x 64 halves, SW128
    int t = threadIdx.x, warp = t >> 5, lane = t & 31;
    int m0 = blockIdx.x * 128;
    int k0 = blockIdx.y * 1024;
    float c[3][4];
#pragma unroll
    for (int nt = 0; nt < 3; nt++)
#pragma unroll
        for (int j = 0; j < 4; j++) c[nt][j] = 0.f;
    int r0 = warp * 16;
    int mrow = r0 + (lane & 7) + ((lane >> 3) & 1) * 8;
    int khalf = ((lane >> 4) & 1) * 16;
    for (int ch = 0; ch < 16; ch++) {
        int kc = k0 + ch * 64;
        __syncthreads();
#pragma unroll
        for (int q = 0; q < 4; q++) {
            int i = t + q * 256;
            int row = i >> 3, u = i & 7;
            uint4 v = *(const uint4 *)(g_Rh + (size_t)(m0 + row) * HC + kc + u * 8);
            int b = (row * 128 + u * 16) ^ ((row & 7) * 16);
            *(uint4 *)(sA + b) = v;
        }
        __syncthreads();
#pragma unroll
        for (int kt = 0; kt < 4; kt++) {
            int b = (mrow * 128 + kt * 32 + khalf) ^ ((mrow & 7) * 16);
            unsigned sa = (unsigned)__cvta_generic_to_shared(sA + b);
            unsigned a0, a1, a2, a3;
            asm volatile("ldmatrix.sync.aligned.m8n8.x4.shared.b16 {%0,%1,%2,%3}, [%4];"
                         : "=r"(a0), "=r"(a1), "=r"(a2), "=r"(a3) : "r"(sa));
            int ktg = ((kc >> 4) + kt) * 3;
#pragma unroll
            for (int nt = 0; nt < 3; nt++) {
                uint2 bh = g_WoHi[(ktg + nt) * 32 + lane];
                uint2 bl = g_WoLo[(ktg + nt) * 32 + lane];
                mma_f16(c[nt][0], c[nt][1], c[nt][2], c[nt][3], a0, a1, a2, a3, bh.x, bh.y);
                mma_f16(c[nt][0], c[nt][1], c[nt][2], c[nt][3], a0, a1, a2, a3, bl.x, bl.y);
            }
        }
    }
    int gid = lane >> 2, tig = lane & 3;
    int row = m0 + r0 + gid;
#pragma unroll
    for (int nt = 0; nt < 3; nt++) {
        int col = nt * 8 + tig * 2;
        if (col < 20) {
            atomicAdd(&out[row * 20 + col], c[nt][0]);
            atomicAdd(&out[(row + 8) * 20 + col], c[nt][2]);
        }
        if (col + 1 < 20) {
            atomicAdd(&out[row * 20 + col + 1], c[nt][1]);
            atomicAdd(&out[(row + 8) * 20 + col + 1], c[nt][3]);
        }
    }
}

extern "C" void kernel_launch(void *const *d_in, const int *in_sizes, int n_in,
                              void *d_out, int out_size) {
    const float *x = (const float *)d_in[0];
    const unsigned *ei = (const unsigned *)d_in[1];
    const float *Wl = (const float *)d_in[2];
    const float *Wr = (const float *)d_in[3];
    const float *att = (const float *)d_in[4];
    const float *bias = (const float *)d_in[5];
    const float *Wout = (const float *)d_in[6];
    const float *bout = (const float *)d_in[7];
    float *out = (float *)d_out;

    pack_a_k<<<256, 256>>>(x);           // 0
    pack_w_k<<<4096, 256>>>(Wl, Wr);     // 1
    detect_k<<<1, 1>>>(ei);              // 2
    gemm_k<<<dim3(512, 16), 256>>>();    // 3  <- ncu capture slot
    loadidx_k<<<64, 256>>>(ei);          // 4
    zero_deg_k<<<16, 256>>>();           // 5
    hist_k<<<64, 256>>>();               // 6
    scan_k<<<1, 1024>>>();               // 7
    scatter_k<<<64, 256>>>();            // 8
    pack_wout_k<<<384, 256>>>(Wout);     // 9
    pack_ab_k<<<64, 256>>>(att, bias);   // 10
    zinit_k<<<320, 256>>>(out, bout);    // 11
    attn_k<<<16384, 128>>>();            // 12
    zout_k<<<dim3(32, 16), 256>>>(out);  // 13
}

// round 7
// speedup vs baseline: 1.1496x; 1.0072x over previous
#include <cuda_runtime.h>
#include <cuda_bf16.h>
#include <cuda_fp16.h>
#include <cstdint>

#define EE 16384
#define NNODE 4096
#define HC 16384

// ------------- static scratch -------------
__device__ __align__(16) __half g_XLRh[(size_t)NNODE * 32768];  // [n][0:16384)=x_l, [16384:)=x_r (phys-permuted cols)
__device__ __align__(16) __half g_Rh[(size_t)NNODE * HC];       // relu(agg + bias), fp16, phys-permuted
__device__ __align__(16) uint4 g_Apack[256 * 8 * 32];           // x tf32 A-fragments [mt][ks][lane]
__device__ __align__(16) uint2 g_Wb[512 * 8 * 8 * 32];          // [W_l|W_r] tf32 B-fragments [nb][nt][ks][lane]
__device__ __align__(8) uint2 g_WoHi[1024 * 3 * 32];            // W_out fp16-hi fragments
__device__ __align__(8) uint2 g_WoLo[1024 * 3 * 32];            // W_out fp16-lo fragments
__device__ __align__(16) float g_attP[HC];                      // att, column-permuted
__device__ __align__(16) float g_biasP[HC];                     // bias, column-permuted
__device__ int g_rowptr[NNODE + 1];
__device__ int g_esrc[EE];
__device__ int g_src[EE];
__device__ int g_dstA[EE];

// ------------- helpers -------------
__device__ __forceinline__ unsigned f2tf32(float f) {
    unsigned r;
    asm("cvt.rna.tf32.f32 %0, %1;" : "=r"(r) : "f"(f));
    return r;
}
__device__ __forceinline__ void mma_tf32(float *c, const uint4 &a, const uint2 &b) {
    asm volatile("mma.sync.aligned.m16n8k8.row.col.f32.tf32.tf32.f32 "
                 "{%0,%1,%2,%3}, {%4,%5,%6,%7}, {%8,%9}, {%0,%1,%2,%3};\n"
                 : "+f"(c[0]), "+f"(c[1]), "+f"(c[2]), "+f"(c[3])
                 : "r"(a.x), "r"(a.y), "r"(a.z), "r"(a.w), "r"(b.x), "r"(b.y));
}
__device__ __forceinline__ void mma_f16(float &c0, float &c1, float &c2, float &c3,
                                        unsigned a0, unsigned a1, unsigned a2, unsigned a3,
                                        unsigned b0, unsigned b1) {
    asm volatile("mma.sync.aligned.m16n8k16.row.col.f32.f16.f16.f32 "
                 "{%0,%1,%2,%3}, {%4,%5,%6,%7}, {%8,%9}, {%0,%1,%2,%3};\n"
                 : "+f"(c0), "+f"(c1), "+f"(c2), "+f"(c3)
                 : "r"(a0), "r"(a1), "r"(a2), "r"(a3), "r"(b0), "r"(b1));
}
__device__ __forceinline__ float lrelu(float v) { return fmaxf(v, 0.f) + 0.2f * fminf(v, 0.f); }
// physical column -> logical column, within each 32-col block
__device__ __forceinline__ int Lr(int r) {
    int p = r & 31;
    return (r & ~31) | ((((p >> 1) & 3) << 3) | (((p >> 3) & 3) << 1) | (p & 1));
}

// ------------- fused packing (W, A, att/bias, W_out) + out init -------------
__global__ void pack_all_k(const float *__restrict__ x, const float *__restrict__ Wl,
                           const float *__restrict__ Wr, const float *__restrict__ att,
                           const float *__restrict__ bias, const float *__restrict__ Wout,
                           const float *__restrict__ bout, float *__restrict__ out) {
    int b = blockIdx.x, t = threadIdx.x;
    if (b < 4096) {  // ---- pack W_l/W_r tf32 B fragments ----
        unsigned u = b * 256u + t;
        int lane = u & 31, ks = (u >> 5) & 7, nt = (u >> 8) & 7;
        int nb = u >> 11;
        int gid = lane >> 2, tig = lane & 3;
        int ncat = nb * 64 + nt * 8 + gid;
        const float *W = (ncat >= HC) ? Wr : Wl;
        int n = ncat & (HC - 1);
        int k0 = ks * 8 + tig;
        uint2 bb;
        bb.x = f2tf32(W[k0 * HC + n]);
        bb.y = f2tf32(W[(k0 + 4) * HC + n]);
        g_Wb[u] = bb;
    } else if (b < 4352) {  // ---- pack A (x) tf32 fragments ----
        int u = (b - 4096) * 256 + t;
        int lane = u & 31, ks = (u >> 5) & 7, mt = u >> 8;
        int gid = lane >> 2, tig = lane & 3;
        const float *r0 = x + (mt * 16 + gid) * 64;
        const float *r1 = r0 + 8 * 64;
        uint4 a;
        a.x = f2tf32(r0[ks * 8 + tig]);
        a.y = f2tf32(r1[ks * 8 + tig]);
        a.z = f2tf32(r0[ks * 8 + tig + 4]);
        a.w = f2tf32(r1[ks * 8 + tig + 4]);
        g_Apack[u] = a;
    } else if (b < 4416) {  // ---- permute att / bias ----
        int c = (b - 4352) * 256 + t;
        int L = Lr(c);
        g_attP[c] = att[L];
        g_biasP[c] = bias[L];
    } else if (b < 4800) {  // ---- pack W_out fp16 hi/lo fragments ----
        int u = (b - 4416) * 256 + t;
        int kt = u / 96, rem = u % 96;
        int nt = rem >> 5, lane = rem & 31;
        int gid = lane >> 2, tig = lane & 3;
        int n = nt * 8 + gid;
        int k0 = kt * 16 + tig * 2;
        float f[4];
        if (n < 20) {
            f[0] = Wout[Lr(k0) * 20 + n];
            f[1] = Wout[Lr(k0 + 1) * 20 + n];
            f[2] = Wout[Lr(k0 + 8) * 20 + n];
            f[3] = Wout[Lr(k0 + 9) * 20 + n];
        } else {
            f[0] = f[1] = f[2] = f[3] = 0.f;
        }
        __half h[4];
        float l[4];
#pragma unroll
        for (int i = 0; i < 4; i++) {
            h[i] = __float2half_rn(f[i]);
            l[i] = f[i] - __half2float(h[i]);
        }
        uint2 bh, bl;
        __half2 t0 = __halves2half2(h[0], h[1]), t1 = __halves2half2(h[2], h[3]);
        bh.x = *(unsigned *)&t0;
        bh.y = *(unsigned *)&t1;
        __half2 t2 = __floats2half2_rn(l[0], l[1]), t3 = __floats2half2_rn(l[2], l[3]);
        bl.x = *(unsigned *)&t2;
        bl.y = *(unsigned *)&t3;
        int o = (kt * 3 + nt) * 32 + lane;
        g_WoHi[o] = bh;
        g_WoLo[o] = bl;
    } else {  // ---- init out with bias ----
        int i = (b - 4800) * 256 + t;  // 81920 exactly
        out[i] = bout[i % 20];
    }
}

// ------------- single-block CSR build (detect + extract + hist + scan + scatter) -------
__global__ void __launch_bounds__(1024) csr_k(const unsigned *__restrict__ w) {
    __shared__ int sdeg[NNODE];
    __shared__ int ssc[1024];
    __shared__ int sflag;
    int t = threadIdx.x;
    if (t == 0) {
        int is64 = 1;
        for (int i = 1; i < 64; i += 2)
            if (w[i] != 0u) { is64 = 0; break; }
        sflag = is64;
    }
    for (int i = t; i < NNODE; i += 1024) sdeg[i] = 0;
    __syncthreads();
    int is64 = sflag;
    for (int e = t; e < EE; e += 1024) {
        int s, d;
        if (is64) {
            s = (int)w[2 * e];
            d = (int)w[2 * (EE + e)];
        } else {
            s = (int)w[e];
            d = (int)w[EE + e];
        }
        s &= NNODE - 1;
        d &= NNODE - 1;
        g_src[e] = s;
        g_dstA[e] = d;
        atomicAdd(&sdeg[d], 1);
    }
    __syncthreads();
    int b = t * 4;
    int d0 = sdeg[b], d1 = sdeg[b + 1], d2 = sdeg[b + 2], d3 = sdeg[b + 3];
    int p1 = d0, p2 = d0 + d1, p3 = p2 + d2, tot = p3 + d3;
    ssc[t] = tot;
    __syncthreads();
    for (int off = 1; off < 1024; off <<= 1) {
        int y = (t >= off) ? ssc[t - off] : 0;
        __syncthreads();
        ssc[t] += y;
        __syncthreads();
    }
    int excl = (t > 0) ? ssc[t - 1] : 0;
    g_rowptr[b] = excl;
    g_rowptr[b + 1] = excl + p1;
    g_rowptr[b + 2] = excl + p2;
    g_rowptr[b + 3] = excl + p3;
    if (t == 1023) g_rowptr[NNODE] = ssc[1023];
    __syncthreads();
    sdeg[b] = excl;
    sdeg[b + 1] = excl + p1;
    sdeg[b + 2] = excl + p2;
    sdeg[b + 3] = excl + p3;
    __syncthreads();
    for (int e = t; e < EE; e += 1024) {
        int d = g_dstA[e];
        int pos = atomicAdd(&sdeg[d], 1);
        g_esrc[pos] = g_src[e];
    }
}

// ------------- GEMM: XLR = x @ [W_l | W_r]  (tf32 single pass, MT=2, coalesced stores)
__global__ void __launch_bounds__(256) gemm_k() {
    __shared__ uint2 sB[2048];  // [nt(8)][ks(8)][lane(32)] = 16KB
    int t = threadIdx.x, warp = t >> 5, lane = t & 31;
    int gid = lane >> 2, tig = lane & 3;
    int nb = blockIdx.x;  // 512: 64 cols each
    int mb = blockIdx.y;  // 16: 256 rows each
    {
        const uint4 *src = (const uint4 *)(g_Wb + nb * 2048);
        uint4 *dst = (uint4 *)sB;
#pragma unroll
        for (int i = 0; i < 4; i++) dst[i * 256 + t] = src[i * 256 + t];
    }
    int mt0 = (mb * 8 + warp) * 2;  // two m-tiles per warp
    uint4 A0[8], A1[8];
#pragma unroll
    for (int ks = 0; ks < 8; ks++) {
        A0[ks] = g_Apack[(mt0 * 8 + ks) * 32 + lane];
        A1[ks] = g_Apack[((mt0 + 1) * 8 + ks) * 32 + lane];
    }
    __syncthreads();
    float c[2][8][4];
#pragma unroll
    for (int m = 0; m < 2; m++)
#pragma unroll
        for (int nt = 0; nt < 8; nt++)
#pragma unroll
            for (int j = 0; j < 4; j++) c[m][nt][j] = 0.f;
#pragma unroll
    for (int nt = 0; nt < 8; nt++) {
#pragma unroll
        for (int ks = 0; ks < 8; ks++) {
            uint2 b = sB[(nt * 8 + ks) * 32 + lane];
            mma_tf32(c[0][nt], A0[ks], b);
            mma_tf32(c[1][nt], A1[ks], b);
        }
    }
#pragma unroll
    for (int m = 0; m < 2; m++) {
        int rbase = (mt0 + m) * 16;
#pragma unroll
        for (int half = 0; half < 2; half++) {
            int row = rbase + gid + half * 8;
            __half *orow = g_XLRh + (size_t)row * 32768 + nb * 64 + tig * 8;
#pragma unroll
            for (int b32 = 0; b32 < 2; b32++) {
                uint4 ou;
                __half2 *op = (__half2 *)&ou;
#pragma unroll
                for (int q = 0; q < 4; q++) {
                    int nt = b32 * 4 + q;
                    op[q] = __floats2half2_rn(c[m][nt][half * 2], c[m][nt][half * 2 + 1]);
                }
                *(uint4 *)(orow + b32 * 32) = ou;
            }
        }
    }
}

// ------------- fused attention: warp per (dst,head), two-phase chunked softmax -------
__global__ void __launch_bounds__(128) attn_k() {
    int w = threadIdx.x >> 5, lane = threadIdx.x & 31;
    int p = blockIdx.x * 4 + w;  // head-major: 65536 pairs
    int h = p >> 12, dst = p & (NNODE - 1);
    const __half *xlbase = g_XLRh + (size_t)h * 1024;
    unsigned xr2[16];
    float at[32], acc[32];
    {
        const uint4 *xr4 = (const uint4 *)(g_XLRh + (size_t)dst * 32768 + HC + h * 1024);
        const float4 *at4 = (const float4 *)(g_attP + h * 1024);
#pragma unroll
        for (int c = 0; c < 4; c++) {
            uint4 v = xr4[c * 32 + lane];
            xr2[c * 4 + 0] = v.x; xr2[c * 4 + 1] = v.y;
            xr2[c * 4 + 2] = v.z; xr2[c * 4 + 3] = v.w;
            float4 a0 = at4[c * 64 + lane * 2], a1 = at4[c * 64 + lane * 2 + 1];
            at[c * 8 + 0] = a0.x; at[c * 8 + 1] = a0.y; at[c * 8 + 2] = a0.z; at[c * 8 + 3] = a0.w;
            at[c * 8 + 4] = a1.x; at[c * 8 + 5] = a1.y; at[c * 8 + 6] = a1.z; at[c * 8 + 7] = a1.w;
        }
    }
#pragma unroll
    for (int j = 0; j < 32; j++) acc[j] = 0.f;
    int rp = g_rowptr[dst];
    int cnt = g_rowptr[dst + 1] - rp + 1;  // edges + self-loop
    float m_run = -1e30f, s_run = 0.f;
    for (int base = 0; base < cnt; base += 64) {
        int n = min(64, cnt - base);
        float L0 = -1e30f, L1 = -1e30f;
        // ---- phase A: independent per-edge logits ----
        for (int i = 0; i < n; i++) {
            int ge = base + i;
            int src = (ge < cnt - 1) ? g_esrc[rp + ge] : dst;
            const uint4 *xl4 = (const uint4 *)(xlbase + (size_t)src * 32768);
            float p0 = 0.f, p1 = 0.f;
#pragma unroll
            for (int c = 0; c < 4; c++) {
                uint4 v = xl4[c * 32 + lane];
                const __half2 *hp = (const __half2 *)&v;
#pragma unroll
                for (int k = 0; k < 4; k++) {
                    __half2 t2 = __hadd2(hp[k], *(const __half2 *)&xr2[c * 4 + k]);
                    float2 tf = __half22float2(t2);
                    p0 = fmaf(at[c * 8 + 2 * k], lrelu(tf.x), p0);
                    p1 = fmaf(at[c * 8 + 2 * k + 1], lrelu(tf.y), p1);
                }
            }
            float pp = p0 + p1;
            pp += __shfl_xor_sync(0xffffffffu, pp, 16);
            pp += __shfl_xor_sync(0xffffffffu, pp, 8);
            pp += __shfl_xor_sync(0xffffffffu, pp, 4);
            pp += __shfl_xor_sync(0xffffffffu, pp, 2);
            pp += __shfl_xor_sync(0xffffffffu, pp, 1);
            if ((i & 31) == lane) {
                if (i < 32) L0 = pp; else L1 = pp;
            }
        }
        // ---- chunk softmax ----
        float mc = fmaxf(L0, L1);
#pragma unroll
        for (int o = 16; o; o >>= 1) mc = fmaxf(mc, __shfl_xor_sync(0xffffffffu, mc, o));
        float m_new = fmaxf(m_run, mc);
        float rs = __expf(m_run - m_new);
        s_run *= rs;
#pragma unroll
        for (int j = 0; j < 32; j++) acc[j] *= rs;
        float W0 = __expf(L0 - m_new), W1 = __expf(L1 - m_new);
        float ls = W0 + W1;
#pragma unroll
        for (int o = 16; o; o >>= 1) ls += __shfl_xor_sync(0xffffffffu, ls, o);
        s_run += ls;
        // ---- phase B: weighted accumulation, no reductions ----
        for (int i = 0; i < n; i++) {
            int ge = base + i;
            int src = (ge < cnt - 1) ? g_esrc[rp + ge] : dst;
            float wgt = __shfl_sync(0xffffffffu, (i < 32) ? W0 : W1, i & 31);
            const uint4 *xl4 = (const uint4 *)(xlbase + (size_t)src * 32768);
#pragma unroll
            for (int c = 0; c < 4; c++) {
                uint4 v = xl4[c * 32 + lane];
                const __half2 *hp = (const __half2 *)&v;
#pragma unroll
                for (int k = 0; k < 4; k++) {
                    float2 f = __half22float2(hp[k]);
                    acc[c * 8 + 2 * k] = fmaf(wgt, f.x, acc[c * 8 + 2 * k]);
                    acc[c * 8 + 2 * k + 1] = fmaf(wgt, f.y, acc[c * 8 + 2 * k + 1]);
                }
            }
        }
        m_run = m_new;
    }
    float inv = 1.f / (s_run + 1e-16f);
    const float4 *b4 = (const float4 *)(g_biasP + h * 1024);
    uint4 *Ro = (uint4 *)(g_Rh + (size_t)dst * HC + h * 1024);
#pragma unroll
    for (int c = 0; c < 4; c++) {
        float4 b0 = b4[c * 64 + lane * 2], b1 = b4[c * 64 + lane * 2 + 1];
        float bi[8] = {b0.x, b0.y, b0.z, b0.w, b1.x, b1.y, b1.z, b1.w};
        uint4 ou;
        __half2 *op = (__half2 *)&ou;
#pragma unroll
        for (int j = 0; j < 4; j++) {
            float v0 = fmaxf(fmaf(acc[c * 8 + 2 * j], inv, bi[2 * j]), 0.f);
            float v1 = fmaxf(fmaf(acc[c * 8 + 2 * j + 1], inv, bi[2 * j + 1]), 0.f);
            op[j] = __floats2half2_rn(v0, v1);
        }
        Ro[c * 32 + lane] = ou;
    }
}

// ------------- output GEMM (tensor core): z = R @ W_out + b_out -------------
__global__ void __launch_bounds__(256) zout_k(float *__restrict__ out) {
    __shared__ __align__(16) char sA[128 * 128];  // 128 rows x 64 halves, SW128
    int t = threadIdx.x, warp = t >> 5, lane = t & 31;
    int m0 = blockIdx.x * 128;
    int k0 = blockIdx.y * 1024;
    float c[3][4];
#pragma unroll
    for (int nt = 0; nt < 3; nt++)
#pragma unroll
        for (int j = 0; j < 4; j++) c[nt][j] = 0.f;
    int r0 = warp * 16;
    int mrow = r0 + (lane & 7) + ((lane >> 3) & 1) * 8;
    int khalf = ((lane >> 4) & 1) * 16;
    for (int ch = 0; ch < 16; ch++) {
        int kc = k0 + ch * 64;
        __syncthreads();
#pragma unroll
        for (int q = 0; q < 4; q++) {
            int i = t + q * 256;
            int row = i >> 3, u = i & 7;
            uint4 v = *(const uint4 *)(g_Rh + (size_t)(m0 + row) * HC + kc + u * 8);
            int b = (row * 128 + u * 16) ^ ((row & 7) * 16);
            *(uint4 *)(sA + b) = v;
        }
        __syncthreads();
#pragma unroll
        for (int kt = 0; kt < 4; kt++) {
            int b = (mrow * 128 + kt * 32 + khalf) ^ ((mrow & 7) * 16);
            unsigned sa = (unsigned)__cvta_generic_to_shared(sA + b);
            unsigned a0, a1, a2, a3;
            asm volatile("ldmatrix.sync.aligned.m8n8.x4.shared.b16 {%0,%1,%2,%3}, [%4];"
                         : "=r"(a0), "=r"(a1), "=r"(a2), "=r"(a3) : "r"(sa));
            int ktg = ((kc >> 4) + kt) * 3;
#pragma unroll
            for (int nt = 0; nt < 3; nt++) {
                uint2 bh = g_WoHi[(ktg + nt) * 32 + lane];
                uint2 bl = g_WoLo[(ktg + nt) * 32 + lane];
                mma_f16(c[nt][0], c[nt][1], c[nt][2], c[nt][3], a0, a1, a2, a3, bh.x, bh.y);
                mma_f16(c[nt][0], c[nt][1], c[nt][2], c[nt][3], a0, a1, a2, a3, bl.x, bl.y);
            }
        }
    }
    int gid = lane >> 2, tig = lane & 3;
    int row = m0 + r0 + gid;
#pragma unroll
    for (int nt = 0; nt < 3; nt++) {
        int col = nt * 8 + tig * 2;
        if (col < 20) {
            atomicAdd(&out[row * 20 + col], c[nt][0]);
            atomicAdd(&out[(row + 8) * 20 + col], c[nt][2]);
        }
        if (col + 1 < 20) {
            atomicAdd(&out[row * 20 + col + 1], c[nt][1]);
            atomicAdd(&out[(row + 8) * 20 + col + 1], c[nt][3]);
        }
    }
}

extern "C" void kernel_launch(void *const *d_in, const int *in_sizes, int n_in,
                              void *d_out, int out_size) {
    const float *x = (const float *)d_in[0];
    const unsigned *ei = (const unsigned *)d_in[1];
    const float *Wl = (const float *)d_in[2];
    const float *Wr = (const float *)d_in[3];
    const float *att = (const float *)d_in[4];
    const float *bias = (const float *)d_in[5];
    const float *Wout = (const float *)d_in[6];
    const float *bout = (const float *)d_in[7];
    float *out = (float *)d_out;

    pack_all_k<<<5120, 256>>>(x, Wl, Wr, att, bias, Wout, bout, out);  // 0
    csr_k<<<1, 1024>>>(ei);                                            // 1
    gemm_k<<<dim3(512, 16), 256>>>();                                  // 2
    attn_k<<<16384, 128>>>();                                          // 3  <- ncu capture slot
    zout_k<<<dim3(32, 16), 256>>>(out);                                // 4
}